// round 9
// baseline (speedup 1.0000x reference)
#include <cuda_runtime.h>
#include <cstdint>

typedef unsigned long long ull;

#define Bsz 1024
#define Tt 64
#define Dd 128
#define Hh 128
#define ATT 64
#define HOR 24
#define G 8
#define NCTAS (Bsz/G)
#define NTHR 1024

// ---------------- device scratch ----------------
__device__ float g_WihT[Dd * 4 * Hh];    // [k][512o]
__device__ float g_WhhT[Hh * 4 * Hh];    // [k][512o]
__device__ float g_WhhTd[Hh * 4 * Hh];   // [k][512o]
__device__ float g_WhsT[256 * 64];       // [k][64a]  We_w[:, :256]^T
__device__ float g_WdsT[256 * 64];       // [k][64a]  Wd_w[:, 128:384]^T
__device__ float g_WdpT[128 * 64];       // [k][64a]  Wd_w[:, :128]^T
__device__ float g_hid[(size_t)Bsz * Tt * Hh];    // [b][t][h]
__device__ float g_proj[(size_t)Bsz * ATT * Tt];  // [b][a][t]

// ---------------- helpers ----------------
__device__ __forceinline__ float tanh_fast(float x) {
    float y; asm("tanh.approx.f32 %0, %1;" : "=f"(y) : "f"(x)); return y;
}
__device__ __forceinline__ float sigm(float x) { return 1.f / (1.f + __expf(-x)); }
__device__ __forceinline__ float tanh_acc(float x) {
    float ax = fabsf(x);
    float e = __expf(-2.f * ax);
    float t = (1.f - e) / (1.f + e);
    return copysignf(t, x);
}
__device__ __forceinline__ ull pack2(float lo, float hi) {
    ull r; asm("mov.b64 %0, {%1,%2};" : "=l"(r) : "f"(lo), "f"(hi)); return r;
}
__device__ __forceinline__ float2 unpack2(ull v) {
    float2 r; asm("mov.b64 {%0,%1}, %2;" : "=f"(r.x), "=f"(r.y) : "l"(v)); return r;
}
__device__ __forceinline__ void ffma2(ull &d, ull a, ull b) {
    asm("fma.rn.f32x2 %0, %1, %2, %0;" : "+l"(d) : "l"(a), "l"(b));
}
__device__ __forceinline__ void bar512() {   // att-group + E2-group barrier
    asm volatile("bar.sync 1, 512;" ::: "memory");
}

// ---------------- prologue: build transposed weights ----------------
__global__ void transpose_k(const float* __restrict__ Wih,
                            const float* __restrict__ Whh,
                            const float* __restrict__ Wdh,
                            const float* __restrict__ We_w,
                            const float* __restrict__ Wd_w) {
    int i = blockIdx.x * blockDim.x + threadIdx.x;
    if (i < 512 * 128) {
        int o = i >> 7, k = i & 127;
        g_WihT[k * 512 + o]  = Wih[i];
        g_WhhT[k * 512 + o]  = Whh[i];
        g_WhhTd[k * 512 + o] = Wdh[i];
    }
    if (i < 256 * 64) {
        int k = i >> 6, a = i & 63;
        g_WhsT[i] = We_w[a * 257 + k];
        g_WdsT[i] = Wd_w[a * 384 + 128 + k];
    }
    if (i < 128 * 64) {
        int k = i >> 6, a = i & 63;
        g_WdpT[i] = Wd_w[a * 384 + k];
    }
}

// smem float offsets
#define OFF_H      0
#define OFF_C      (OFF_H + 1024)
#define OFF_XD     (OFF_C + 1024)     // x_tilde dup (enc) / context plain (dec)
#define OFF_HD     (OFF_XD + 2048)
#define OFF_CD     (OFF_HD + 2048)
#define OFF_BASE   (OFF_CD + 2048)
#define OFF_SC     (OFF_BASE + 512)
#define OFF_GA     (OFF_SC + 512)     // Wih partial kh=0 (also proj stage lo)
#define OFF_GB     (OFF_GA + 4096)    // Whh full (also proj stage hi)
#define OFF_GC     (OFF_GB + 4096)    // Wih partial kh=1
#define OFF_BIAS   (OFF_GC + 4096)
#define OFF_WEB    (OFF_BIAS + 512)
#define OFF_WV     (OFF_WEB + 64)
#define OFF_WDB    (OFF_WV + 128)
#define OFF_VDW    (OFF_WDB + 64)
#define OFF_DWIH   (OFF_VDW + 64)
#define OFF_FCW    (OFF_DWIH + 512)
#define OFF_YH     (OFF_FCW + 320)
#define OFF_YPREV  (OFF_YH + 512)
#define SMEM_FLOATS (OFF_YPREV + 8)
#define SMEM_BYTES  (SMEM_FLOATS * 4)

__global__ void __launch_bounds__(NTHR, 1)
darnn_kernel(const float* __restrict__ X,        const float* __restrict__ y_hist,
             const float* __restrict__ We_w,     const float* __restrict__ We_b,
             const float* __restrict__ ve_w,     const float* __restrict__ ve_b,
             const float* __restrict__ enc_bih,  const float* __restrict__ enc_bhh,
             const float* __restrict__ dec_Wih,  const float* __restrict__ dec_bih,
             const float* __restrict__ dec_bhh,
             const float* __restrict__ Wd_w,     const float* __restrict__ Wd_b,
             const float* __restrict__ vd_w,     const float* __restrict__ vd_b,
             const float* __restrict__ fc_w,     const float* __restrict__ fc_b,
             float* __restrict__ out) {
    extern __shared__ float sm[];
    float* s_h     = sm + OFF_H;
    float* s_c     = sm + OFF_C;
    float* s_xd    = sm + OFF_XD;
    float* s_hd    = sm + OFF_HD;
    float* s_cd    = sm + OFF_CD;
    float* s_base  = sm + OFF_BASE;
    float* s_sc    = sm + OFF_SC;
    float* s_gA    = sm + OFF_GA;
    float* s_gB    = sm + OFF_GB;
    float* s_gC    = sm + OFF_GC;
    float* s_bias  = sm + OFF_BIAS;
    float* s_Web   = sm + OFF_WEB;
    float* s_wv    = sm + OFF_WV;
    float* s_Wdb   = sm + OFF_WDB;
    float* s_vdw   = sm + OFF_VDW;
    float* s_dWih  = sm + OFF_DWIH;
    float* s_fcw   = sm + OFF_FCW;
    float* s_yh    = sm + OFF_YH;
    float* s_yprev = sm + OFF_YPREV;

    const int tid  = threadIdx.x;
    const int lane = tid & 31;
    const int wrp  = tid >> 5;
    const int la   = lane;
    const int b0   = blockIdx.x * G;
    const int gU   = tid >> 7;          // update: batch row
    const int uU   = tid & 127;         // update: unit
    const float ve_b_r = ve_b[0];

    // ---------- preload ----------
    if (tid < 512) s_bias[tid] = enc_bih[tid] + enc_bhh[tid];
    if (tid < 64) {
        s_Web[tid] = We_b[tid];
        ((float2*)s_wv)[tid] = make_float2(We_w[tid * 257 + 256], ve_w[tid]);
    }
    if (tid < 512) s_yh[tid] = y_hist[b0 * Tt + tid];
    for (int i = tid; i < 1024; i += NTHR) { s_h[i] = 0.f; s_c[i] = 0.f; }
    for (int i = tid; i < 2048; i += NTHR) { s_hd[i] = 0.f; s_cd[i] = 0.f; }
    __syncthreads();

    const ull* WihP  = reinterpret_cast<const ull*>(g_WihT);
    const ull* WhhP  = reinterpret_cast<const ull*>(g_WhhT);
    const ull* WhhPd = reinterpret_cast<const ull*>(g_WhhTd);
    const ull* WhsP  = reinterpret_cast<const ull*>(g_WhsT);
    const ull* WdsP  = reinterpret_cast<const ull*>(g_WdsT);
    const ull* WdpP  = reinterpret_cast<const ull*>(g_WdpT);

    // ================= ENCODER: 64 steps =================
    for (int t = 0; t < Tt; ++t) {
        if (wrp < 8) {
            // ---- attention warps: wait for base, then E3/E4 ----
            const int r = wrp;
            const float* Xg = X + ((size_t)(b0 + r) * Tt + t) * Dd;
            float xv0 = Xg[la], xv1 = Xg[la + 32], xv2 = Xg[la + 64], xv3 = Xg[la + 96];
            bar512();
            float s0 = ve_b_r, s1 = ve_b_r, s2 = ve_b_r, s3 = ve_b_r;
            const float* bg = s_base + r * 64;
            const float2* wv = (const float2*)s_wv;
            #pragma unroll 8
            for (int a = 0; a < 64; ++a) {
                float ba = bg[a];
                float2 w = wv[a];
                s0 = fmaf(w.y, tanh_fast(fmaf(xv0, w.x, ba)), s0);
                s1 = fmaf(w.y, tanh_fast(fmaf(xv1, w.x, ba)), s1);
                s2 = fmaf(w.y, tanh_fast(fmaf(xv2, w.x, ba)), s2);
                s3 = fmaf(w.y, tanh_fast(fmaf(xv3, w.x, ba)), s3);
            }
            float m = fmaxf(fmaxf(s0, s1), fmaxf(s2, s3));
            #pragma unroll
            for (int o = 16; o; o >>= 1) m = fmaxf(m, __shfl_xor_sync(0xffffffffu, m, o));
            float e0 = __expf(s0 - m), e1 = __expf(s1 - m);
            float e2 = __expf(s2 - m), e3 = __expf(s3 - m);
            float ss = (e0 + e1) + (e2 + e3);
            #pragma unroll
            for (int o = 16; o; o >>= 1) ss += __shfl_xor_sync(0xffffffffu, ss, o);
            float inv = 1.f / ss;
            float* xd = s_xd + r * 256;
            float v0 = xv0 * e0 * inv, v1 = xv1 * e1 * inv;
            float v2 = xv2 * e2 * inv, v3 = xv3 * e3 * inv;
            *(float2*)(xd + 2 * la)       = make_float2(v0, v0);
            *(float2*)(xd + 2 * la + 64)  = make_float2(v1, v1);
            *(float2*)(xd + 2 * la + 128) = make_float2(v2, v2);
            *(float2*)(xd + 2 * la + 192) = make_float2(v3, v3);
        } else if (wrp < 24) {
            // ---- Whh · h -> s_gB : 512 thr, op x g-half, full k ----
            const int idx = tid - 256;
            const int op = idx & 255, gh = idx >> 8;
            const ull* Wp = WhhP + op;
            ull acc[4];
            #pragma unroll
            for (int q = 0; q < 4; ++q) acc[q] = 0ULL;
            const float* hb = s_hd + gh * 4 * 256;
            #pragma unroll 4
            for (int kp = 0; kp < 64; ++kp) {
                ull w0 = Wp[(2 * kp) * 256];
                ull w1 = Wp[(2 * kp + 1) * 256];
                #pragma unroll
                for (int q = 0; q < 4; ++q) {
                    ulonglong2 hp = *(const ulonglong2*)(hb + q * 256 + 4 * kp);
                    ffma2(acc[q], w0, hp.x);
                    ffma2(acc[q], w1, hp.y);
                }
            }
            #pragma unroll
            for (int q = 0; q < 4; ++q) {
                float2 r2 = unpack2(acc[q]);
                *(float2*)(s_gB + (gh * 4 + q) * 512 + 2 * op) = r2;
            }
        } else {
            // ---- E2 gemm-style: base = We_b + [h;c]·Whs^T ----
            const int idx = tid - 768;
            const int ap = idx & 31, g = idx >> 5;
            const ull* Wp = WhsP + ap;
            float2 wb = ((const float2*)s_Web)[ap];
            ull aA = pack2(wb.x, wb.y), aB = 0ULL;
            #pragma unroll 8
            for (int k = 0; k < 128; k += 2) {
                ulonglong2 hp = *(const ulonglong2*)(s_hd + g * 256 + 2 * k);
                ffma2(aA, Wp[k * 32], hp.x);
                ffma2(aB, Wp[(k + 1) * 32], hp.y);
            }
            #pragma unroll 8
            for (int k = 0; k < 128; k += 2) {
                ulonglong2 cp = *(const ulonglong2*)(s_cd + g * 256 + 2 * k);
                ffma2(aA, Wp[(128 + k) * 32], cp.x);
                ffma2(aB, Wp[(129 + k) * 32], cp.y);
            }
            float2 ra = unpack2(aA), rb = unpack2(aB);
            *(float2*)(s_base + g * 64 + 2 * ap) = make_float2(ra.x + rb.x, ra.y + rb.y);
            bar512();
        }
        __syncthreads();
        // ---- Wih · x_tilde : all 1024 thr, (op, kh, gh) ----
        {
            const int op = tid & 255, kh = (tid >> 8) & 1, gh = tid >> 9;
            const ull* Wp = WihP + kh * 64 * 256 + op;
            float* dst = kh ? s_gC : s_gA;
            const float* ab = s_xd + gh * 4 * 256 + kh * 128;
            ull acc[4];
            #pragma unroll
            for (int q = 0; q < 4; ++q) acc[q] = 0ULL;
            #pragma unroll 4
            for (int kp = 0; kp < 32; ++kp) {
                ull w0 = Wp[(2 * kp) * 256];
                ull w1 = Wp[(2 * kp + 1) * 256];
                #pragma unroll
                for (int q = 0; q < 4; ++q) {
                    ulonglong2 xp = *(const ulonglong2*)(ab + q * 256 + 4 * kp);
                    ffma2(acc[q], w0, xp.x);
                    ffma2(acc[q], w1, xp.y);
                }
            }
            #pragma unroll
            for (int q = 0; q < 4; ++q) {
                float2 r2 = unpack2(acc[q]);
                *(float2*)(dst + (gh * 4 + q) * 512 + 2 * op) = r2;
            }
        }
        __syncthreads();
        // ---- LSTM update: 1 unit per thread ----
        {
            float pre[4];
            #pragma unroll
            for (int q = 0; q < 4; ++q) {
                int idx = gU * 512 + q * 128 + uU;
                pre[q] = (s_gA[idx] + s_gB[idx]) + (s_gC[idx] + s_bias[q * 128 + uU]);
            }
            float ig = sigm(pre[0]);
            float fg = sigm(pre[1]);
            float gv = tanh_acc(pre[2]);
            float og = sigm(pre[3]);
            float c2 = fmaf(fg, s_c[gU * 128 + uU], ig * gv);
            float h2 = og * tanh_acc(c2);
            s_c[gU * 128 + uU] = c2;
            s_h[gU * 128 + uU] = h2;
            *(float2*)(s_hd + gU * 256 + 2 * uU) = make_float2(h2, h2);
            *(float2*)(s_cd + gU * 256 + 2 * uU) = make_float2(c2, c2);
            g_hid[((size_t)(b0 + gU) * Tt + t) * Hh + uU] = h2;
        }
        __syncthreads();
    }

    // ================= enc_proj: 4 timesteps per iter =================
    {
        float* stg = s_gA;    // 8192 floats contiguous (gA + gB)
        for (int it = 0; it < 16; ++it) {
            const int t0 = it * 4;
            #pragma unroll
            for (int j = 0; j < 4; ++j) {
                int flat = tid + j * 1024;
                int t_l = flat >> 10, rem = flat & 1023;
                int g = rem >> 7, k = rem & 127;
                float v = g_hid[((size_t)(b0 + g) * Tt + t0 + t_l) * Hh + k];
                *(float2*)(stg + t_l * 2048 + g * 256 + 2 * k) = make_float2(v, v);
            }
            __syncthreads();
            {
                const int t_l = tid >> 8;
                const int idx = tid & 255;
                const int ap = idx & 31, g = idx >> 5;
                const ull* Wp = WdpP + ap;
                const float* hb = stg + t_l * 2048 + g * 256;
                ull aA = 0ULL, aB = 0ULL;
                #pragma unroll 8
                for (int k = 0; k < 128; k += 2) {
                    ulonglong2 hp = *(const ulonglong2*)(hb + 2 * k);
                    ffma2(aA, Wp[k * 32], hp.x);
                    ffma2(aB, Wp[(k + 1) * 32], hp.y);
                }
                float2 ra = unpack2(aA), rb = unpack2(aB);
                int tcur = t0 + t_l;
                float* pb = g_proj + (size_t)(b0 + g) * ATT * Tt + tcur;
                pb[(2 * ap) * Tt]     = ra.x + rb.x;
                pb[(2 * ap + 1) * Tt] = ra.y + rb.y;
            }
            __syncthreads();
        }
    }

    // ---------- decoder preload ----------
    if (tid < 512) {
        s_bias[tid] = dec_bih[tid] + dec_bhh[tid];
        s_dWih[tid] = dec_Wih[tid];
    }
    if (tid < 64) { s_Wdb[tid] = Wd_b[tid]; s_vdw[tid] = vd_w[tid]; }
    if (tid < 320) s_fcw[tid] = fc_w[tid];
    for (int i = tid; i < 1024; i += NTHR) { s_h[i] = 0.f; s_c[i] = 0.f; }
    for (int i = tid; i < 2048; i += NTHR) { s_hd[i] = 0.f; s_cd[i] = 0.f; }
    if (tid < 8) s_yprev[tid] = s_yh[tid * 64 + 63];
    const float vd_b_r = vd_b[0];
    const float fc_b_r = fc_b[0];
    __syncthreads();

    auto do_D7 = [&](int s) {
        const int r = wrp;
        float acc = 0.f;
        #pragma unroll
        for (int itr = 0; itr < 10; ++itr) {
            int idx = lane + itr * 32;
            float v;
            if (idx < 128)      v = s_h[r * 128 + idx];
            else if (idx < 256) v = s_xd[r * 128 + idx - 128];
            else                v = s_yh[r * 64 + idx - 256];
            acc = fmaf(s_fcw[idx], v, acc);
        }
        #pragma unroll
        for (int o = 16; o; o >>= 1) acc += __shfl_xor_sync(0xffffffffu, acc, o);
        if (lane == 0) {
            float ov = acc + fc_b_r;
            s_yprev[r] = ov;
            out[(b0 + r) * HOR + s] = ov;
        }
    };

    // ================= DECODER: 24 steps =================
    for (int s = 0; s < HOR; ++s) {
        if (wrp < 8) {
            const int r = wrp;
            if (s > 0) do_D7(s - 1);
            bar512();
            // D2+D3: temporal scores + softmax
            {
                const float* pp = g_proj + (size_t)(b0 + r) * ATT * Tt;
                const float* bg = s_base + r * 64;
                float ac0 = vd_b_r, ac1 = vd_b_r;
                #pragma unroll 4
                for (int a = 0; a < 64; ++a) {
                    float dca = bg[a];
                    float vw = s_vdw[a];
                    ac0 = fmaf(vw, tanh_fast(pp[a * 64 + la] + dca), ac0);
                    ac1 = fmaf(vw, tanh_fast(pp[a * 64 + la + 32] + dca), ac1);
                }
                float m = fmaxf(ac0, ac1);
                #pragma unroll
                for (int o = 16; o; o >>= 1) m = fmaxf(m, __shfl_xor_sync(0xffffffffu, m, o));
                float e0 = __expf(ac0 - m), e1 = __expf(ac1 - m);
                float ss = e0 + e1;
                #pragma unroll
                for (int o = 16; o; o >>= 1) ss += __shfl_xor_sync(0xffffffffu, ss, o);
                float inv = 1.f / ss;
                s_sc[r * 64 + la]      = e0 * inv;
                s_sc[r * 64 + la + 32] = e1 * inv;
            }
            __syncwarp();
            // D4: context -> s_xd (plain, 4 units/lane)
            {
                const int u4 = 4 * la;
                const float4* hp4 = (const float4*)(g_hid + (size_t)(b0 + r) * Tt * Hh + u4);
                const float* be = s_sc + r * 64;
                float4 acc4 = make_float4(0.f, 0.f, 0.f, 0.f);
                #pragma unroll 4
                for (int tt = 0; tt < 64; ++tt) {
                    float b = be[tt];
                    float4 hv = hp4[tt * 32];
                    acc4.x = fmaf(b, hv.x, acc4.x);
                    acc4.y = fmaf(b, hv.y, acc4.y);
                    acc4.z = fmaf(b, hv.z, acc4.z);
                    acc4.w = fmaf(b, hv.w, acc4.w);
                }
                *(float4*)(s_xd + r * 128 + u4) = acc4;
            }
        } else if (wrp < 24) {
            // D5: Whh_dec · d -> s_gB
            const int idx = tid - 256;
            const int op = idx & 255, gh = idx >> 8;
            const ull* Wp = WhhPd + op;
            ull acc[4];
            #pragma unroll
            for (int q = 0; q < 4; ++q) acc[q] = 0ULL;
            const float* hb = s_hd + gh * 4 * 256;
            #pragma unroll 4
            for (int kp = 0; kp < 64; ++kp) {
                ull w0 = Wp[(2 * kp) * 256];
                ull w1 = Wp[(2 * kp + 1) * 256];
                #pragma unroll
                for (int q = 0; q < 4; ++q) {
                    ulonglong2 hp = *(const ulonglong2*)(hb + q * 256 + 4 * kp);
                    ffma2(acc[q], w0, hp.x);
                    ffma2(acc[q], w1, hp.y);
                }
            }
            #pragma unroll
            for (int q = 0; q < 4; ++q) {
                float2 r2 = unpack2(acc[q]);
                *(float2*)(s_gB + (gh * 4 + q) * 512 + 2 * op) = r2;
            }
        } else {
            // D1 gemm-style: dc = Wd_b + [d;c]·Wds^T
            const int idx = tid - 768;
            const int ap = idx & 31, g = idx >> 5;
            const ull* Wp = WdsP + ap;
            float2 wb = ((const float2*)s_Wdb)[ap];
            ull aA = pack2(wb.x, wb.y), aB = 0ULL;
            #pragma unroll 8
            for (int k = 0; k < 128; k += 2) {
                ulonglong2 hp = *(const ulonglong2*)(s_hd + g * 256 + 2 * k);
                ffma2(aA, Wp[k * 32], hp.x);
                ffma2(aB, Wp[(k + 1) * 32], hp.y);
            }
            #pragma unroll 8
            for (int k = 0; k < 128; k += 2) {
                ulonglong2 cp = *(const ulonglong2*)(s_cd + g * 256 + 2 * k);
                ffma2(aA, Wp[(128 + k) * 32], cp.x);
                ffma2(aB, Wp[(129 + k) * 32], cp.y);
            }
            float2 ra = unpack2(aA), rb = unpack2(aB);
            *(float2*)(s_base + g * 64 + 2 * ap) = make_float2(ra.x + rb.x, ra.y + rb.y);
            bar512();
        }
        __syncthreads();
        // D6: update (gB + bias + dWih * y_prev)
        {
            float y = s_yprev[gU];
            float pre[4];
            #pragma unroll
            for (int q = 0; q < 4; ++q) {
                int iq = q * 128 + uU;
                pre[q] = fmaf(s_dWih[iq], y, s_gB[gU * 512 + iq] + s_bias[iq]);
            }
            float ig = sigm(pre[0]);
            float fg = sigm(pre[1]);
            float gv = tanh_acc(pre[2]);
            float og = sigm(pre[3]);
            float c2 = fmaf(fg, s_c[gU * 128 + uU], ig * gv);
            float h2 = og * tanh_acc(c2);
            s_c[gU * 128 + uU] = c2;
            s_h[gU * 128 + uU] = h2;
            *(float2*)(s_hd + gU * 256 + 2 * uU) = make_float2(h2, h2);
            *(float2*)(s_cd + gU * 256 + 2 * uU) = make_float2(c2, c2);
        }
        __syncthreads();
    }
    if (wrp < 8) do_D7(HOR - 1);
}

extern "C" void kernel_launch(void* const* d_in, const int* in_sizes, int n_in,
                              void* d_out, int out_size) {
    const float* X        = (const float*)d_in[0];
    const float* y_hist   = (const float*)d_in[1];
    const float* We_w     = (const float*)d_in[2];
    const float* We_b     = (const float*)d_in[3];
    const float* ve_w     = (const float*)d_in[4];
    const float* ve_b     = (const float*)d_in[5];
    const float* enc_Wih  = (const float*)d_in[6];
    const float* enc_Whh  = (const float*)d_in[7];
    const float* enc_bih  = (const float*)d_in[8];
    const float* enc_bhh  = (const float*)d_in[9];
    const float* dec_Wih  = (const float*)d_in[10];
    const float* dec_Whh  = (const float*)d_in[11];
    const float* dec_bih  = (const float*)d_in[12];
    const float* dec_bhh  = (const float*)d_in[13];
    const float* Wd_w     = (const float*)d_in[14];
    const float* Wd_b     = (const float*)d_in[15];
    const float* vd_w     = (const float*)d_in[16];
    const float* vd_b     = (const float*)d_in[17];
    const float* fc_w     = (const float*)d_in[18];
    const float* fc_b     = (const float*)d_in[19];
    float* out = (float*)d_out;

    cudaFuncSetAttribute(darnn_kernel,
                         cudaFuncAttributeMaxDynamicSharedMemorySize, SMEM_BYTES);

    transpose_k<<<(512 * 128 + 255) / 256, 256>>>(enc_Wih, enc_Whh, dec_Whh, We_w, Wd_w);
    darnn_kernel<<<NCTAS, NTHR, SMEM_BYTES>>>(
        X, y_hist, We_w, We_b, ve_w, ve_b,
        enc_bih, enc_bhh, dec_Wih, dec_bih, dec_bhh,
        Wd_w, Wd_b, vd_w, vd_b, fc_w, fc_b, out);
}